// round 1
// baseline (speedup 1.0000x reference)
#include <cuda_runtime.h>
#include <cstdint>

#define N_ANCH 102000
#define ROWLEN 85
#define CONF 0.25f
#define IOUT 0.45f
#define TOPK 8192
#define KW 128            // 8192/64 mask words per row
#define MAXDET 300
#define CAP 16384
#define NBIN 8192         // 13-bit histogram

typedef unsigned long long u64;
typedef unsigned int u32;

// ---------------- static device scratch (no allocations allowed) ----------------
__device__ u64 g_keys[N_ANCH];
__device__ u32 g_cls[N_ANCH];
__device__ u32 g_hist[NBIN];
__device__ int g_thrbin;
__device__ int g_cnt;
__device__ u64 g_ckeys[CAP];
__device__ u32 g_rank[CAP];
__device__ u64 g_topkeys[TOPK];
__device__ float4 g_boxes[TOPK];
__device__ float g_scores[TOPK];
__device__ float g_classes[TOPK];
__device__ u64 g_validm[KW];
__device__ u64 g_mask[(size_t)TOPK * KW];   // 8 MB
__device__ int g_kept[MAXDET];
__device__ int g_nkept;

// ---------------- K0: zero the per-call state ----------------
__global__ void k_init() {
    int t = blockIdx.x * blockDim.x + threadIdx.x;
    if (t < NBIN) g_hist[t] = 0u;
    if (t < CAP) { g_ckeys[t] = 0ULL; g_rank[t] = 0u; }
    if (t < TOPK) g_topkeys[t] = 0ULL;
    if (t < KW) g_validm[t] = 0ULL;
    if (t == 0) { g_cnt = 0; g_nkept = 0; g_thrbin = 0; }
}

// ---------------- K1: per-anchor score/class, key build, histogram ----------------
// One warp per anchor. score = (obj > CONF) ? max_c(p[5+c]*obj) : 0, argmax first-tie.
__global__ void k_score(const float* __restrict__ preds) {
    int warp = (blockIdx.x * blockDim.x + threadIdx.x) >> 5;
    int lane = threadIdx.x & 31;
    if (warp >= N_ANCH) return;
    const float* p = preds + (size_t)warp * ROWLEN;
    float e0 = p[lane];
    float e1 = p[lane + 32];
    float e2 = (lane < ROWLEN - 64) ? p[lane + 64] : 0.0f;   // lane < 21
    float obj = __shfl_sync(0xffffffffu, e0, 4);

    float bv = -1.0f; int bc = 0;
    if (lane >= 5) { float v = e0 * obj; if (v > bv) { bv = v; bc = lane - 5; } }
    {               float v = e1 * obj; if (v > bv) { bv = v; bc = lane + 27; } }
    if (lane < 21) { float v = e2 * obj; if (v > bv) { bv = v; bc = lane + 59; } }

    #pragma unroll
    for (int off = 16; off; off >>= 1) {
        float ov = __shfl_xor_sync(0xffffffffu, bv, off);
        int   oc = __shfl_xor_sync(0xffffffffu, bc, off);
        if (ov > bv || (ov == bv && oc < bc)) { bv = ov; bc = oc; }
    }
    if (lane == 0) {
        float s = (obj > CONF) ? bv : 0.0f;
        u32 sb = __float_as_uint(s);
        g_keys[warp] = ((u64)sb << 32) | (u64)(0xFFFFFFFFu - (u32)warp);
        g_cls[warp]  = (u32)bc;
        atomicAdd(&g_hist[sb >> 19], 1u);
    }
}

// ---------------- K3: find threshold bin (largest T with suffix count >= TOPK) ----------------
__global__ void k_thresh() {
    __shared__ u32 part[1024];
    int t = threadIdx.x;
    u32 s = 0;
    #pragma unroll
    for (int b = 0; b < 8; b++) s += g_hist[t * 8 + b];
    part[t] = s;
    __syncthreads();
    for (int off = 1; off < 1024; off <<= 1) {   // suffix sum
        u32 v = part[t] + ((t + off < 1024) ? part[t + off] : 0u);
        __syncthreads();
        part[t] = v;
        __syncthreads();
    }
    u32 suf = part[t];
    u32 sufNext = (t < 1023) ? part[t + 1] : 0u;
    if (suf >= TOPK && sufNext < TOPK) {
        u32 acc = sufNext;
        for (int b = 7; b >= 0; b--) {
            acc += g_hist[t * 8 + b];
            if (acc >= TOPK) { g_thrbin = t * 8 + b; break; }
        }
    }
    if (t == 0 && part[0] < TOPK) g_thrbin = 0;
}

// ---------------- K4: compact candidates with bin >= threshold ----------------
__global__ void k_compact() {
    int i = blockIdx.x * blockDim.x + threadIdx.x;
    if (i >= N_ANCH) return;
    u64 k = g_keys[i];
    int bin = (int)(k >> 51);
    if (bin >= g_thrbin) {
        int pos = atomicAdd(&g_cnt, 1);
        if (pos < CAP) g_ckeys[pos] = k;
    }
}

// ---------------- K5: all-pairs rank (rank = # larger keys) ----------------
__global__ void k_rank() {
    __shared__ u64 sj[2048];
    int ich = blockIdx.x, jch = blockIdx.y;
    int t = threadIdx.x;
    for (int j = t; j < 2048; j += 256) sj[j] = g_ckeys[jch * 2048 + j];
    __syncthreads();
    u64 ki[8]; u32 r[8];
    #pragma unroll
    for (int k = 0; k < 8; k++) { ki[k] = g_ckeys[ich * 2048 + k * 256 + t]; r[k] = 0; }
    for (int j = 0; j < 2048; j++) {
        u64 kj = sj[j];
        #pragma unroll
        for (int k = 0; k < 8; k++) r[k] += (kj > ki[k]) ? 1u : 0u;
    }
    #pragma unroll
    for (int k = 0; k < 8; k++) atomicAdd(&g_rank[ich * 2048 + k * 256 + t], r[k]);
}

__global__ void k_scatter() {
    int i = blockIdx.x * blockDim.x + threadIdx.x;
    if (i >= CAP) return;
    u32 r = g_rank[i];
    if (r < TOPK) g_topkeys[r] = g_ckeys[i];
}

// ---------------- K6: gather boxes/scores/classes for top-8192 ----------------
__global__ void k_gather(const float* __restrict__ preds) {
    int r = blockIdx.x * blockDim.x + threadIdx.x;
    if (r >= TOPK) return;
    u64 key = g_topkeys[r];
    float s = __uint_as_float((u32)(key >> 32));
    u32 idx = 0xFFFFFFFFu - (u32)key;
    bool valid = (s > 0.0f) && (idx < N_ANCH);
    if (idx >= N_ANCH) idx = 0;
    const float* p = preds + (size_t)idx * ROWLEN;
    float x = p[0], y = p[1], w = p[2], h = p[3];
    float4 b;
    b.x = y - h * 0.5f;  // y1
    b.y = x - w * 0.5f;  // x1
    b.z = y + h * 0.5f;  // y2
    b.w = x + w * 0.5f;  // x2
    g_boxes[r] = b;
    g_scores[r] = s;
    g_classes[r] = (float)g_cls[idx];
    if (valid) atomicOr(&g_validm[r >> 6], 1ULL << (r & 63));
}

// ---------------- K7: IoU bitmask (upper-triangular 64x64 blocks) ----------------
__global__ void k_mask() {
    int cy = blockIdx.y, cx = blockIdx.x;
    if (cx < cy) return;
    int t = threadIdx.x;  // 0..63
    __shared__ float4 sb[64];
    __shared__ float sa[64];
    float4 jb = g_boxes[cx * 64 + t];
    sb[t] = jb;
    sa[t] = (jb.z - jb.x) * (jb.w - jb.y);
    float4 ib = g_boxes[cy * 64 + t];
    float ai = (ib.z - ib.x) * (ib.w - ib.y);
    __syncthreads();
    u64 bits = 0;
    int jstart = (cx == cy) ? t + 1 : 0;
    for (int j = jstart; j < 64; j++) {
        float4 b2 = sb[j];
        float ty = fmaxf(ib.x, b2.x);
        float tx = fmaxf(ib.y, b2.y);
        float by = fminf(ib.z, b2.z);
        float bx = fminf(ib.w, b2.w);
        float inter = fmaxf(by - ty, 0.0f) * fmaxf(bx - tx, 0.0f);
        float uni = ai + sa[j] - inter;
        float iou = inter / (uni + 1e-9f);
        if (iou > IOUT) bits |= (1ULL << j);
    }
    g_mask[(size_t)(cy * 64 + t) * KW + cx] = bits;
}

// ---------------- K8: serial greedy scan, early-stop at 300 keepers ----------------
__global__ void k_scan() {
    int t = threadIdx.x;  // 128 threads, thread w owns remv word w
    __shared__ u64 sAlive;
    u64 remv = 0;
    int nk = 0;
    bool done = false;
    for (int c = 0; c < KW && !done; c++) {
        if (t == c) sAlive = (~remv) & g_validm[c];
        __syncthreads();
        while (true) {
            u64 a = sAlive;
            if (a == 0ULL) break;
            int bit = __ffsll((long long)a) - 1;
            int i = (c << 6) + bit;
            u64 row = (t >= c) ? g_mask[(size_t)i * KW + t] : 0ULL;
            remv |= row;
            if (t == 0) g_kept[nk] = i;
            nk++;
            if (t == c) sAlive = a & ~(1ULL << bit) & ~row;
            __syncthreads();
            if (nk >= MAXDET) { done = true; break; }
        }
        __syncthreads();
    }
    if (t == 0) g_nkept = nk;
}

// ---------------- K9: write 300 detections (boxes, classes, scores) ----------------
__global__ void k_out(float* __restrict__ out) {
    int s = blockIdx.x * blockDim.x + threadIdx.x;
    if (s >= MAXDET) return;
    int nk = g_nkept;
    float4 b = make_float4(0.f, 0.f, 0.f, 0.f);
    float cls = 0.f, sc = 0.f;
    if (s < nk) {
        int i = g_kept[s];
        b = g_boxes[i];
        cls = g_classes[i];
        sc = g_scores[i];
    }
    out[s * 4 + 0] = b.x;
    out[s * 4 + 1] = b.y;
    out[s * 4 + 2] = b.z;
    out[s * 4 + 3] = b.w;
    out[MAXDET * 4 + s] = cls;
    out[MAXDET * 5 + s] = sc;
}

extern "C" void kernel_launch(void* const* d_in, const int* in_sizes, int n_in,
                              void* d_out, int out_size) {
    const float* preds = (const float*)d_in[0];
    float* out = (float*)d_out;

    k_init<<<64, 256>>>();
    k_score<<<(N_ANCH + 7) / 8, 256>>>(preds);
    k_thresh<<<1, 1024>>>();
    k_compact<<<(N_ANCH + 255) / 256, 256>>>();
    k_rank<<<dim3(8, 8), 256>>>();
    k_scatter<<<64, 256>>>();
    k_gather<<<32, 256>>>(preds);
    k_mask<<<dim3(128, 128), 64>>>();
    k_scan<<<1, 128>>>();
    k_out<<<2, 256>>>(out);
}

// round 2
// speedup vs baseline: 2.0695x; 2.0695x over previous
#include <cuda_runtime.h>
#include <cstdint>

#define N_ANCH 102000
#define ROWLEN 85
#define CONF 0.25f
#define IOUT 0.45f
#define TOPK 8192
#define KW 128            // 8192/64 mask words per row (full fallback)
#define KWS 16            // 1024/64 words, small fast-path mask
#define NSMALL 1024
#define MAXDET 300
#define CAP 9216          // 36*256, candidate cap after 16-bit histogram select
#define NBIN 65536

typedef unsigned long long u64;
typedef unsigned int u32;

// ---------------- static device scratch ----------------
__device__ u64 g_keys[N_ANCH];
__device__ u32 g_cls[N_ANCH];
__device__ u32 g_hist[NBIN];
__device__ int g_thrbin;
__device__ int g_cnt;
__device__ u64 g_ckeys[CAP];
__device__ u32 g_rank[CAP];
__device__ u64 g_topkeys[TOPK];
__device__ float4 g_boxes[TOPK];
__device__ float g_scores[TOPK];
__device__ float g_classes[TOPK];
__device__ u64 g_validm[KW];
__device__ u64 g_maskS[(size_t)NSMALL * KWS];   // 128 KB fast path
__device__ u64 g_mask[(size_t)TOPK * KW];       // 8 MB fallback
__device__ int g_kept[MAXDET];
__device__ int g_nkept;
__device__ int g_done;

// ---------------- K0: zero per-call state ----------------
__global__ void k_init() {
    int t = blockIdx.x * blockDim.x + threadIdx.x;   // 65536 threads
    g_hist[t] = 0u;
    if (t < CAP) { g_ckeys[t] = 0ULL; g_rank[t] = 0u; }
    if (t < TOPK) g_topkeys[t] = 0ULL;
    if (t < KW) g_validm[t] = 0ULL;
    if (t == 0) { g_cnt = 0; g_nkept = 0; g_thrbin = 0; g_done = 0; }
}

// ---------------- K1: score/class + key + 16-bit histogram ----------------
__global__ void k_score(const float* __restrict__ preds) {
    int warp = (blockIdx.x * blockDim.x + threadIdx.x) >> 5;
    int lane = threadIdx.x & 31;
    if (warp >= N_ANCH) return;
    const float* p = preds + (size_t)warp * ROWLEN;
    float e0 = p[lane];
    float obj = __shfl_sync(0xffffffffu, e0, 4);
    u32 sb = 0; int bc = 0;
    if (obj > CONF) {
        float e1 = p[lane + 32];
        float e2 = (lane < 21) ? p[lane + 64] : 0.0f;
        float bv = -1.0f;
        if (lane >= 5) { bv = e0 * obj; bc = lane - 5; }
        float v1 = e1 * obj;
        if (v1 > bv) { bv = v1; bc = lane + 27; }
        if (lane < 21) { float v2 = e2 * obj; if (v2 > bv) { bv = v2; bc = lane + 59; } }
        u32 vb = __float_as_uint(bv);              // bv >= 0 for all lanes
        u32 m = __reduce_max_sync(0xffffffffu, vb);
        u32 cm = __reduce_min_sync(0xffffffffu, (vb == m) ? (u32)bc : 0xFFFFu);
        sb = m; bc = (int)cm;
    }
    if (lane == 0) {
        g_keys[warp] = ((u64)sb << 32) | (u64)(0xFFFFFFFFu - (u32)warp);
        g_cls[warp] = (u32)bc;
        if (sb) atomicAdd(&g_hist[sb >> 16], 1u);
    }
}

// ---------------- K2: threshold bin over 65536 bins ----------------
__global__ void k_thresh() {
    __shared__ u32 part[1024];
    int t = threadIdx.x;
    u32 s = 0;
    #pragma unroll
    for (int b = 0; b < 64; b++) s += g_hist[t * 64 + b];
    part[t] = s;
    __syncthreads();
    for (int off = 1; off < 1024; off <<= 1) {   // suffix sum
        u32 v = part[t] + ((t + off < 1024) ? part[t + off] : 0u);
        __syncthreads();
        part[t] = v;
        __syncthreads();
    }
    u32 suf = part[t];
    u32 sufNext = (t < 1023) ? part[t + 1] : 0u;
    if (suf >= TOPK && sufNext < TOPK) {
        u32 acc = sufNext;
        for (int b = 63; b >= 0; b--) {
            acc += g_hist[t * 64 + b];
            if (acc >= TOPK) { g_thrbin = t * 64 + b; break; }
        }
    }
    if (t == 0 && part[0] < TOPK) g_thrbin = 0;
}

// ---------------- K3: compact (warp-aggregated atomic) ----------------
__global__ void k_compact() {
    int i = blockIdx.x * blockDim.x + threadIdx.x;
    bool take = false; u64 k = 0;
    if (i < N_ANCH) {
        k = g_keys[i];
        take = ((int)(k >> 48) >= g_thrbin) && ((u32)(k >> 32) != 0u);
    }
    u32 bal = __ballot_sync(0xffffffffu, take);
    if (!bal) return;
    int lane = threadIdx.x & 31;
    int leader = __ffs(bal) - 1;
    int pos0 = 0;
    if (lane == leader) pos0 = atomicAdd(&g_cnt, __popc(bal));
    pos0 = __shfl_sync(0xffffffffu, pos0, leader);
    if (take) {
        int pos = pos0 + __popc(bal & ((1u << lane) - 1u));
        if (pos < CAP) g_ckeys[pos] = k;
    }
}

// ---------------- K4: all-pairs rank ----------------
#define RCHI 1024
#define RCHJ 768
__global__ void k_rank() {
    __shared__ u64 sj[RCHJ];
    int t = threadIdx.x;
    int ibase = blockIdx.x * RCHI;
    int jbase = blockIdx.y * RCHJ;
    for (int j = t; j < RCHJ; j += 256) sj[j] = g_ckeys[jbase + j];
    __syncthreads();
    u64 ki[4]; u32 r[4];
    #pragma unroll
    for (int q = 0; q < 4; q++) { ki[q] = g_ckeys[ibase + q * 256 + t]; r[q] = 0; }
    #pragma unroll 4
    for (int j = 0; j < RCHJ; j++) {
        u64 kj = sj[j];
        #pragma unroll
        for (int q = 0; q < 4; q++) r[q] += (kj > ki[q]) ? 1u : 0u;
    }
    #pragma unroll
    for (int q = 0; q < 4; q++) atomicAdd(&g_rank[ibase + q * 256 + t], r[q]);
}

__global__ void k_scatter() {
    int i = blockIdx.x * blockDim.x + threadIdx.x;
    if (i >= CAP) return;
    u32 r = g_rank[i];
    if (r < TOPK) g_topkeys[r] = g_ckeys[i];
}

// ---------------- K5: gather ----------------
__global__ void k_gather(const float* __restrict__ preds) {
    int r = blockIdx.x * blockDim.x + threadIdx.x;
    if (r >= TOPK) return;
    u64 key = g_topkeys[r];
    float s = __uint_as_float((u32)(key >> 32));
    u32 idx = 0xFFFFFFFFu - (u32)key;
    bool valid = (s > 0.0f) && (idx < N_ANCH);
    if (idx >= N_ANCH) idx = 0;
    const float* p = preds + (size_t)idx * ROWLEN;
    float x = p[0], y = p[1], w = p[2], h = p[3];
    float4 b;
    b.x = y - h * 0.5f;
    b.y = x - w * 0.5f;
    b.z = y + h * 0.5f;
    b.w = x + w * 0.5f;
    g_boxes[r] = b;
    g_scores[r] = s;
    g_classes[r] = (float)g_cls[idx];
    if (valid) atomicOr(&g_validm[r >> 6], 1ULL << (r & 63));
}

// ---------------- IoU helper (exact reference arithmetic) ----------------
__device__ __forceinline__ u64 iou_bits(float4 ib, float ai, const float4* sb4,
                                        const float* sa, int jstart) {
    u64 bits = 0;
    for (int j = jstart; j < 64; j++) {
        float4 b2 = sb4[j];
        float ty = fmaxf(ib.x, b2.x);
        float tx = fmaxf(ib.y, b2.y);
        float by = fminf(ib.z, b2.z);
        float bx = fminf(ib.w, b2.w);
        float inter = fmaxf(by - ty, 0.0f) * fmaxf(bx - tx, 0.0f);
        float uni = ai + sa[j] - inter;
        float iou = inter / (uni + 1e-9f);
        if (iou > IOUT) bits |= (1ULL << j);
    }
    return bits;
}

// ---------------- K6a: fast-path mask (top 1024 x 1024) ----------------
__global__ void k_maskS() {
    int cy = blockIdx.y, cx = blockIdx.x;
    if (cx < cy) return;
    int t = threadIdx.x;
    __shared__ float4 sb4[64];
    __shared__ float sa[64];
    float4 jb = g_boxes[cx * 64 + t];
    sb4[t] = jb;
    sa[t] = (jb.z - jb.x) * (jb.w - jb.y);
    float4 ib = g_boxes[cy * 64 + t];
    float ai = (ib.z - ib.x) * (ib.w - ib.y);
    __syncthreads();
    u64 bits = iou_bits(ib, ai, sb4, sa, (cx == cy) ? t + 1 : 0);
    g_maskS[(size_t)(cy * 64 + t) * KWS + cx] = bits;
}

// ---------------- K6b: fast-path serial scan (single warp, smem mask) ----------------
__global__ void k_scanS() {
    extern __shared__ u64 srow[];            // NSMALL*KWS = 16384 u64 = 128 KB
    __shared__ u64 sVtail;
    int t = threadIdx.x;                     // 512 threads
    if (t == 0) sVtail = 0ULL;
    __syncthreads();
    for (int i = t; i < NSMALL * KWS; i += 512) srow[i] = g_maskS[i];
    u64 vt = 0;
    for (int w = KWS + t; w < KW; w += 512) vt |= g_validm[w];
    if (vt) atomicOr(&sVtail, vt);
    __syncthreads();
    if (t >= 32) return;
    int lane = t;
    u64 avail = (lane < KWS) ? g_validm[lane] : 0ULL;
    int nk = 0;
    bool exhausted = false;
    while (nk < MAXDET) {
        u32 bal = __ballot_sync(0xffffffffu, avail != 0ULL);
        if (!bal) { exhausted = true; break; }
        int c = __ffs(bal) - 1;
        u64 ac = __shfl_sync(0xffffffffu, avail, c);
        int bit = __ffsll((long long)ac) - 1;
        int i = (c << 6) + bit;
        u64 row = (lane >= c && lane < KWS) ? srow[i * KWS + lane] : 0ULL;
        avail &= ~row;
        if (lane == c) avail &= ~(1ULL << bit);
        if (lane == 0) g_kept[nk] = i;
        nk++;
    }
    if (lane == 0) {
        g_nkept = nk;
        g_done = (nk >= MAXDET || (exhausted && sVtail == 0ULL)) ? 1 : 0;
    }
}

// ---------------- K7a: fallback full mask (gated) ----------------
__global__ void k_maskF() {
    if (g_done) return;
    int cy = blockIdx.y, cx = blockIdx.x;
    if (cx < cy) return;
    int t = threadIdx.x;
    __shared__ float4 sb4[64];
    __shared__ float sa[64];
    float4 jb = g_boxes[cx * 64 + t];
    sb4[t] = jb;
    sa[t] = (jb.z - jb.x) * (jb.w - jb.y);
    float4 ib = g_boxes[cy * 64 + t];
    float ai = (ib.z - ib.x) * (ib.w - ib.y);
    __syncthreads();
    u64 bits = iou_bits(ib, ai, sb4, sa, (cx == cy) ? t + 1 : 0);
    g_mask[(size_t)(cy * 64 + t) * KW + cx] = bits;
}

// ---------------- K7b: fallback full scan (gated) ----------------
__global__ void k_scanF() {
    if (g_done) return;
    int t = threadIdx.x;  // 128
    __shared__ u64 sAlive;
    u64 remv = 0;
    int nk = 0;
    bool done = false;
    for (int c = 0; c < KW && !done; c++) {
        if (t == c) sAlive = (~remv) & g_validm[c];
        __syncthreads();
        while (true) {
            u64 a = sAlive;
            if (a == 0ULL) break;
            int bit = __ffsll((long long)a) - 1;
            int i = (c << 6) + bit;
            u64 row = (t >= c) ? g_mask[(size_t)i * KW + t] : 0ULL;
            remv |= row;
            if (t == 0) g_kept[nk] = i;
            nk++;
            if (t == c) sAlive = a & ~(1ULL << bit) & ~row;
            __syncthreads();
            if (nk >= MAXDET) { done = true; break; }
        }
        __syncthreads();
    }
    if (t == 0) g_nkept = nk;
}

// ---------------- K8: write output ----------------
__global__ void k_out(float* __restrict__ out) {
    int s = blockIdx.x * blockDim.x + threadIdx.x;
    if (s >= MAXDET) return;
    int nk = g_nkept;
    float4 b = make_float4(0.f, 0.f, 0.f, 0.f);
    float cls = 0.f, sc = 0.f;
    if (s < nk) {
        int i = g_kept[s];
        b = g_boxes[i];
        cls = g_classes[i];
        sc = g_scores[i];
    }
    out[s * 4 + 0] = b.x;
    out[s * 4 + 1] = b.y;
    out[s * 4 + 2] = b.z;
    out[s * 4 + 3] = b.w;
    out[MAXDET * 4 + s] = cls;
    out[MAXDET * 5 + s] = sc;
}

extern "C" void kernel_launch(void* const* d_in, const int* in_sizes, int n_in,
                              void* d_out, int out_size) {
    const float* preds = (const float*)d_in[0];
    float* out = (float*)d_out;

    static int smem_set = 0;
    if (!smem_set) {
        cudaFuncSetAttribute(k_scanS, cudaFuncAttributeMaxDynamicSharedMemorySize,
                             NSMALL * KWS * sizeof(u64));
        smem_set = 1;
    }

    k_init<<<256, 256>>>();
    k_score<<<(N_ANCH + 7) / 8, 256>>>(preds);
    k_thresh<<<1, 1024>>>();
    k_compact<<<(N_ANCH + 255) / 256, 256>>>();
    k_rank<<<dim3(CAP / RCHI, CAP / RCHJ), 256>>>();
    k_scatter<<<CAP / 256, 256>>>();
    k_gather<<<TOPK / 256, 256>>>(preds);
    k_maskS<<<dim3(16, 16), 64>>>();
    k_scanS<<<1, 512, NSMALL * KWS * sizeof(u64)>>>();
    k_maskF<<<dim3(128, 128), 64>>>();
    k_scanF<<<1, 128>>>();
    k_out<<<2, 256>>>(out);
}